// round 16
// baseline (speedup 1.0000x reference)
#include <cuda_runtime.h>
#include <cuda_bf16.h>
#include <mma.h>
#include <cstdint>

using namespace nvcuda;

#define BATCH 4
#define SEQ 2048
#define DM 1024
#define NH 16
#define HD 64
#define MROWS (BATCH * SEQ)  // 8192

typedef __nv_bfloat16 bf16;

// Scratch (alloc-free rule: __device__ globals)
__device__ float g_O[(size_t)MROWS * DM];
__device__ bf16  g_Wh[(size_t)4 * DM * DM];
__device__ bf16  g_Wl[(size_t)4 * DM * DM];
__device__ bf16  g_QKVh[(size_t)3 * MROWS * DM];
__device__ bf16  g_QKVl[(size_t)3 * MROWS * DM];

// ======================= W builder (all 4 projections) =======================
__global__ void build_w_all(const float* __restrict__ c0, const float* __restrict__ c1,
                            const float* __restrict__ c2, const float* __restrict__ c3,
                            bf16* __restrict__ wh, bf16* __restrict__ wl) {
    const float* c = (blockIdx.y == 0) ? c0 : (blockIdx.y == 1) ? c1
                   : (blockIdx.y == 2) ? c2 : c3;
    const size_t off = (size_t)blockIdx.y * DM * DM;
    const int n = blockIdx.x;
    for (int k = threadIdx.x; k < DM; k += 256) {
        float v = c[(n - k) & (DM - 1)];
        bf16 h = __float2bfloat16(v);
        wh[off + (size_t)n * DM + k] = h;
        wl[off + (size_t)n * DM + k] = __float2bfloat16(v - __bfloat162float(h));
    }
}

// ======================= wmma bf16 GEMM (3xBF16, cp.async, pass-reordered) ==============
// Y[m][n] = sum_k X[m][k] * W[n][k] + bias[n]
// BM=128, BN=128, BK=32. 256 threads = 8 warps (4m x 2n), warp tile 32x64.
#define GLD 40
#define GEMM_SMEM 90368

__device__ __forceinline__ void cpasync16(void* smem_dst, const void* gsrc) {
    uint32_t s = (uint32_t)__cvta_generic_to_shared(smem_dst);
    asm volatile("cp.async.cg.shared.global [%0], [%1], 16;" :: "r"(s), "l"(gsrc));
}

template<int MODE>
__global__ __launch_bounds__(256, 2) void gemm_wmma(
    const float* __restrict__ X, const bf16* __restrict__ WhB,
    const bf16* __restrict__ WlB,
    const float* __restrict__ b0, const float* __restrict__ b1,
    const float* __restrict__ b2,
    float* __restrict__ Y, bf16* __restrict__ YhB, bf16* __restrict__ YlB)
{
    extern __shared__ __align__(16) char pool[];

    const int z = blockIdx.z;
    const bf16* Wh = WhB + (size_t)z * DM * DM;
    const bf16* Wl = WlB + (size_t)z * DM * DM;
    const float* bias = (z == 0) ? b0 : (z == 1) ? b1 : b2;
    const float scale = (MODE == 1 && z == 0) ? 0.125f : 1.0f;
    bf16* Yh = YhB + (size_t)z * MROWS * DM;
    bf16* Yl = YlB + (size_t)z * MROWS * DM;

    float (*bias_s)[132] = (float(*)[132])(pool + 81920);
    float* Sg = (float*)pool;

    const int tid = threadIdx.x;
    const int wid = tid >> 5;
    const int wm = wid >> 1;   // 0..3
    const int wn = wid & 1;    // 0..1

    const int bm = blockIdx.y * 128;
    const int bn = blockIdx.x * 128;

    for (int rep = 0; rep < 8; ++rep) {
        const int lin = tid + rep * 256;
        bias_s[lin >> 7][lin & 127] = bias[bn + (lin & 127)];
    }
    __syncthreads();

    wmma::fragment<wmma::accumulator, 16, 16, 16, float> C[2][4];
#pragma unroll
    for (int mi = 0; mi < 2; ++mi)
#pragma unroll
        for (int ni = 0; ni < 4; ++ni)
            wmma::load_matrix_sync(C[mi][ni], &bias_s[0][wn * 64 + ni * 16], 132,
                                   wmma::mem_row_major);
    __syncthreads();

    const int r4 = tid >> 3;
    const int c4 = (tid & 7) * 4;
    const int rB = tid >> 1;
    const int ce = (tid & 1) * 16;

    float4 avr[4];
    {
        const float* xp = X + (size_t)(bm + r4) * DM + c4;
#pragma unroll
        for (int rep = 0; rep < 4; ++rep)
            avr[rep] = *(const float4*)(xp + (size_t)rep * 32 * DM);
        char* bb = pool + 40960;
        cpasync16(bb + rB * 80 + ce * 2,              Wh + (size_t)(bn + rB) * DM + ce);
        cpasync16(bb + rB * 80 + ce * 2 + 16,         Wh + (size_t)(bn + rB) * DM + ce + 8);
        cpasync16(bb + 10240 + rB * 80 + ce * 2,      Wl + (size_t)(bn + rB) * DM + ce);
        cpasync16(bb + 10240 + rB * 80 + ce * 2 + 16, Wl + (size_t)(bn + rB) * DM + ce + 8);
        asm volatile("cp.async.commit_group;" ::: "memory");
    }

    for (int chunk = 0; chunk < 32; ++chunk) {
        const int p = chunk & 1;
        char* aB = pool + p * 20480;
        asm volatile("cp.async.wait_group 0;" ::: "memory");

#pragma unroll
        for (int rep = 0; rep < 4; ++rep) {
            const int row = r4 + rep * 32;
            float4 v = avr[rep];
            bf16 h0 = __float2bfloat16(v.x), h1 = __float2bfloat16(v.y);
            bf16 h2 = __float2bfloat16(v.z), h3 = __float2bfloat16(v.w);
            __nv_bfloat162* ph = (__nv_bfloat162*)(aB + row * 80 + c4 * 2);
            ph[0] = __nv_bfloat162(h0, h1);
            ph[1] = __nv_bfloat162(h2, h3);
            __nv_bfloat162* pl = (__nv_bfloat162*)(aB + 10240 + row * 80 + c4 * 2);
            pl[0] = __nv_bfloat162(__float2bfloat16(v.x - __bfloat162float(h0)),
                                   __float2bfloat16(v.y - __bfloat162float(h1)));
            pl[1] = __nv_bfloat162(__float2bfloat16(v.z - __bfloat162float(h2)),
                                   __float2bfloat16(v.w - __bfloat162float(h3)));
        }
        __syncthreads();

        if (chunk + 1 < 32) {
            const int kt = (chunk + 1) * 32;
            const float* xp = X + (size_t)(bm + r4) * DM + kt + c4;
#pragma unroll
            for (int rep = 0; rep < 4; ++rep)
                avr[rep] = *(const float4*)(xp + (size_t)rep * 32 * DM);
            char* bb = pool + 40960 + (p ^ 1) * 20480;
            cpasync16(bb + rB * 80 + ce * 2,              Wh + (size_t)(bn + rB) * DM + kt + ce);
            cpasync16(bb + rB * 80 + ce * 2 + 16,         Wh + (size_t)(bn + rB) * DM + kt + ce + 8);
            cpasync16(bb + 10240 + rB * 80 + ce * 2,      Wl + (size_t)(bn + rB) * DM + kt + ce);
            cpasync16(bb + 10240 + rB * 80 + ce * 2 + 16, Wl + (size_t)(bn + rB) * DM + kt + ce + 8);
            asm volatile("cp.async.commit_group;" ::: "memory");
        }

        const bf16* Ahp = (const bf16*)(pool + p * 20480);
        const bf16* Alp = (const bf16*)(pool + p * 20480 + 10240);
        const bf16* Bhp = (const bf16*)(pool + 40960 + p * 20480);
        const bf16* Blp = (const bf16*)(pool + 40960 + p * 20480 + 10240);
#pragma unroll
        for (int ks = 0; ks < 2; ++ks) {
            wmma::fragment<wmma::matrix_a, 16, 16, 16, bf16, wmma::row_major> ah[2], al[2];
#pragma unroll
            for (int mi = 0; mi < 2; ++mi) {
                wmma::load_matrix_sync(ah[mi], Ahp + (wm * 32 + mi * 16) * GLD + ks * 16, GLD);
                wmma::load_matrix_sync(al[mi], Alp + (wm * 32 + mi * 16) * GLD + ks * 16, GLD);
            }
#pragma unroll
            for (int nh = 0; nh < 2; ++nh) {
                wmma::fragment<wmma::matrix_b, 16, 16, 16, bf16, wmma::col_major> bh[2], bl[2];
#pragma unroll
                for (int nj = 0; nj < 2; ++nj) {
                    wmma::load_matrix_sync(bh[nj], Bhp + (wn * 64 + (nh * 2 + nj) * 16) * GLD + ks * 16, GLD);
                    wmma::load_matrix_sync(bl[nj], Blp + (wn * 64 + (nh * 2 + nj) * 16) * GLD + ks * 16, GLD);
                }
                // pass-reordered: dependent mma on same C are 4 apart
#pragma unroll
                for (int mi = 0; mi < 2; ++mi)
#pragma unroll
                    for (int nj = 0; nj < 2; ++nj)
                        wmma::mma_sync(C[mi][nh * 2 + nj], ah[mi], bh[nj], C[mi][nh * 2 + nj]);
#pragma unroll
                for (int mi = 0; mi < 2; ++mi)
#pragma unroll
                    for (int nj = 0; nj < 2; ++nj)
                        wmma::mma_sync(C[mi][nh * 2 + nj], ah[mi], bl[nj], C[mi][nh * 2 + nj]);
#pragma unroll
                for (int mi = 0; mi < 2; ++mi)
#pragma unroll
                    for (int nj = 0; nj < 2; ++nj)
                        wmma::mma_sync(C[mi][nh * 2 + nj], al[mi], bh[nj], C[mi][nh * 2 + nj]);
            }
        }
    }

    if (MODE == 0) {
#pragma unroll
        for (int mi = 0; mi < 2; ++mi)
#pragma unroll
            for (int ni = 0; ni < 4; ++ni)
                wmma::store_matrix_sync(Y + (size_t)(bm + wm * 32 + mi * 16) * DM
                                          + bn + wn * 64 + ni * 16,
                                        C[mi][ni], DM, wmma::mem_row_major);
    } else {
        __syncthreads();
#pragma unroll
        for (int mi = 0; mi < 2; ++mi)
#pragma unroll
            for (int ni = 0; ni < 4; ++ni)
                wmma::store_matrix_sync(&Sg[(wm * 32 + mi * 16) * 132 + wn * 64 + ni * 16],
                                        C[mi][ni], 132, wmma::mem_row_major);
        __syncthreads();
        const int row = tid >> 1;
        const int cc = (tid & 1) * 64;
        const size_t gb = (size_t)(bm + row) * DM + bn + cc;
#pragma unroll
        for (int g = 0; g < 8; ++g) {
            uint4 oh, ol;
            __nv_bfloat162* phh = (__nv_bfloat162*)&oh;
            __nv_bfloat162* pll = (__nv_bfloat162*)&ol;
#pragma unroll
            for (int j = 0; j < 4; ++j) {
                float v0 = Sg[row * 132 + cc + g * 8 + j * 2 + 0] * scale;
                float v1 = Sg[row * 132 + cc + g * 8 + j * 2 + 1] * scale;
                bf16 h0 = __float2bfloat16(v0);
                bf16 h1 = __float2bfloat16(v1);
                phh[j] = __nv_bfloat162(h0, h1);
                pll[j] = __nv_bfloat162(__float2bfloat16(v0 - __bfloat162float(h0)),
                                        __float2bfloat16(v1 - __bfloat162float(h1)));
            }
            *(uint4*)(Yh + gb + g * 8) = oh;
            *(uint4*)(Yl + gb + g * 8) = ol;
        }
    }
}

// ======================= wmma flash attention (pass-reordered mma) =======================
#define AQ 72
#define AS 68
#define ATT_SMEM 110592

__global__ __launch_bounds__(256, 2) void attn_wmma(
    const bf16* __restrict__ Qh, const bf16* __restrict__ Ql,
    const bf16* __restrict__ Kh, const bf16* __restrict__ Kl,
    const bf16* __restrict__ Vh, const bf16* __restrict__ Vl,
    float* __restrict__ O)
{
    extern __shared__ char smp[];
    bf16* sQh = (bf16*)(smp);
    bf16* sQl = (bf16*)(smp + 18432);
    bf16* sKh = (bf16*)(smp + 36864);
    bf16* sKl = (bf16*)(smp + 46080);
    bf16* sVh = (bf16*)(smp + 55296);
    bf16* sVl = (bf16*)(smp + 64512);
    float* sS = (float*)(smp + 73728);
    bf16* sPh = (bf16*)(smp + 73728);
    bf16* sPl = (bf16*)(smp + 92160);

    const int tid = threadIdx.x;
    const int wid = tid >> 5;
    const int wm = wid >> 1;
    const int wn = wid & 1;

    const int b = blockIdx.y >> 4;
    const int h = blockIdx.y & 15;
    const int q0 = blockIdx.x * 128;
    const size_t base = (size_t)b * SEQ * DM + h * HD;

    {
        const int r = tid >> 1;
        const int c0 = (tid & 1) * 32;
        const size_t g = base + (size_t)(q0 + r) * DM + c0;
        uint4* dh = (uint4*)(sQh + r * AQ + c0);
        uint4* dl = (uint4*)(sQl + r * AQ + c0);
#pragma unroll
        for (int i = 0; i < 4; ++i) {
            dh[i] = *(const uint4*)(Qh + g + i * 8);
            dl[i] = *(const uint4*)(Ql + g + i * 8);
        }
    }

    const int row = tid >> 1;
    const int cc = (tid & 1) * 32;
    float lr = 0.f;

    wmma::fragment<wmma::accumulator, 16, 16, 16, float> Of[2][2];
#pragma unroll
    for (int mi = 0; mi < 2; ++mi)
#pragma unroll
        for (int ni = 0; ni < 2; ++ni) wmma::fill_fragment(Of[mi][ni], 0.f);

    for (int nt = 0; nt < SEQ; nt += 64) {
        {
            const int r = tid >> 2;
            const int c0 = (tid & 3) * 16;
            const size_t g = base + (size_t)(nt + r) * DM + c0;
            uint4* kh = (uint4*)(sKh + r * AQ + c0);
            uint4* kl = (uint4*)(sKl + r * AQ + c0);
            uint4* vh = (uint4*)(sVh + r * AQ + c0);
            uint4* vl = (uint4*)(sVl + r * AQ + c0);
#pragma unroll
            for (int i = 0; i < 2; ++i) {
                kh[i] = *(const uint4*)(Kh + g + i * 8);
                kl[i] = *(const uint4*)(Kl + g + i * 8);
                vh[i] = *(const uint4*)(Vh + g + i * 8);
                vl[i] = *(const uint4*)(Vl + g + i * 8);
            }
        }
        __syncthreads();

        // S = Q K^T (3-pass, pass-reordered)
        {
            wmma::fragment<wmma::accumulator, 16, 16, 16, float> S[2][2];
#pragma unroll
            for (int mi = 0; mi < 2; ++mi)
#pragma unroll
                for (int ni = 0; ni < 2; ++ni) wmma::fill_fragment(S[mi][ni], 0.f);
#pragma unroll
            for (int ks = 0; ks < 4; ++ks) {
                wmma::fragment<wmma::matrix_a, 16, 16, 16, bf16, wmma::row_major> ah[2], al[2];
                wmma::fragment<wmma::matrix_b, 16, 16, 16, bf16, wmma::col_major> bh[2], bl[2];
#pragma unroll
                for (int mi = 0; mi < 2; ++mi) {
                    wmma::load_matrix_sync(ah[mi], sQh + (wm * 32 + mi * 16) * AQ + ks * 16, AQ);
                    wmma::load_matrix_sync(al[mi], sQl + (wm * 32 + mi * 16) * AQ + ks * 16, AQ);
                }
#pragma unroll
                for (int ni = 0; ni < 2; ++ni) {
                    wmma::load_matrix_sync(bh[ni], sKh + (wn * 32 + ni * 16) * AQ + ks * 16, AQ);
                    wmma::load_matrix_sync(bl[ni], sKl + (wn * 32 + ni * 16) * AQ + ks * 16, AQ);
                }
#pragma unroll
                for (int mi = 0; mi < 2; ++mi)
#pragma unroll
                    for (int ni = 0; ni < 2; ++ni)
                        wmma::mma_sync(S[mi][ni], ah[mi], bh[ni], S[mi][ni]);
#pragma unroll
                for (int mi = 0; mi < 2; ++mi)
#pragma unroll
                    for (int ni = 0; ni < 2; ++ni)
                        wmma::mma_sync(S[mi][ni], ah[mi], bl[ni], S[mi][ni]);
#pragma unroll
                for (int mi = 0; mi < 2; ++mi)
#pragma unroll
                    for (int ni = 0; ni < 2; ++ni)
                        wmma::mma_sync(S[mi][ni], al[mi], bh[ni], S[mi][ni]);
            }
#pragma unroll
            for (int mi = 0; mi < 2; ++mi)
#pragma unroll
                for (int ni = 0; ni < 2; ++ni)
                    wmma::store_matrix_sync(&sS[(wm * 32 + mi * 16) * AS + wn * 32 + ni * 16],
                                            S[mi][ni], AS, wmma::mem_row_major);
        }
        __syncthreads();

        float sv[32];
#pragma unroll
        for (int g = 0; g < 8; ++g)
            *(float4*)&sv[g * 4] = *(const float4*)&sS[row * AS + cc + g * 4];
        __syncthreads();  // WAR: all S reads done before P overwrites union

        {
            float part = 0.f;
#pragma unroll
            for (int j = 0; j < 32; ++j) {
                sv[j] = __expf(sv[j]);
                part += sv[j];
            }
            lr += part;
#pragma unroll
            for (int j = 0; j < 32; j += 2) {
                bf16 h0 = __float2bfloat16(sv[j]);
                bf16 h1 = __float2bfloat16(sv[j + 1]);
                *(__nv_bfloat162*)&sPh[row * AQ + cc + j] = __nv_bfloat162(h0, h1);
                *(__nv_bfloat162*)&sPl[row * AQ + cc + j] =
                    __nv_bfloat162(__float2bfloat16(sv[j] - __bfloat162float(h0)),
                                   __float2bfloat16(sv[j + 1] - __bfloat162float(h1)));
            }
        }
        __syncthreads();

        // O += P V (3-pass, pass-reordered)
#pragma unroll
        for (int ks = 0; ks < 4; ++ks) {
            wmma::fragment<wmma::matrix_a, 16, 16, 16, bf16, wmma::row_major> ah[2], al[2];
            wmma::fragment<wmma::matrix_b, 16, 16, 16, bf16, wmma::row_major> bh[2], bl[2];
#pragma unroll
            for (int mi = 0; mi < 2; ++mi) {
                wmma::load_matrix_sync(ah[mi], sPh + (wm * 32 + mi * 16) * AQ + ks * 16, AQ);
                wmma::load_matrix_sync(al[mi], sPl + (wm * 32 + mi * 16) * AQ + ks * 16, AQ);
            }
#pragma unroll
            for (int ni = 0; ni < 2; ++ni) {
                wmma::load_matrix_sync(bh[ni], sVh + (ks * 16) * AQ + wn * 32 + ni * 16, AQ);
                wmma::load_matrix_sync(bl[ni], sVl + (ks * 16) * AQ + wn * 32 + ni * 16, AQ);
            }
#pragma unroll
            for (int mi = 0; mi < 2; ++mi)
#pragma unroll
                for (int ni = 0; ni < 2; ++ni)
                    wmma::mma_sync(Of[mi][ni], ah[mi], bh[ni], Of[mi][ni]);
#pragma unroll
            for (int mi = 0; mi < 2; ++mi)
#pragma unroll
                for (int ni = 0; ni < 2; ++ni)
                    wmma::mma_sync(Of[mi][ni], ah[mi], bl[ni], Of[mi][ni]);
#pragma unroll
            for (int mi = 0; mi < 2; ++mi)
#pragma unroll
                for (int ni = 0; ni < 2; ++ni)
                    wmma::mma_sync(Of[mi][ni], al[mi], bh[ni], Of[mi][ni]);
        }
        __syncthreads();
    }

    // epilogue
#pragma unroll
    for (int mi = 0; mi < 2; ++mi)
#pragma unroll
        for (int ni = 0; ni < 2; ++ni)
            wmma::store_matrix_sync(&sS[(wm * 32 + mi * 16) * AS + wn * 32 + ni * 16],
                                    Of[mi][ni], AS, wmma::mem_row_major);
    __syncthreads();

    lr += __shfl_xor_sync(0xffffffffu, lr, 1);
    const float inv = 1.f / lr;
    float* op = O + base + (size_t)(q0 + row) * DM + cc;
#pragma unroll
    for (int g = 0; g < 8; ++g) {
        float4 v = *(const float4*)&sS[row * AS + cc + g * 4];
        v.x *= inv; v.y *= inv; v.z *= inv; v.w *= inv;
        *(float4*)(op + g * 4) = v;
    }
}

// ---------------------------------------------------------------------------
extern "C" void kernel_launch(void* const* d_in, const int* in_sizes, int n_in,
                              void* d_out, int out_size)
{
    const float* x    = (const float*)d_in[0];
    const float* wq_c = (const float*)d_in[1];
    const float* wq_b = (const float*)d_in[2];
    const float* wk_c = (const float*)d_in[3];
    const float* wk_b = (const float*)d_in[4];
    const float* wv_c = (const float*)d_in[5];
    const float* wv_b = (const float*)d_in[6];
    const float* wo_c = (const float*)d_in[7];
    const float* wo_b = (const float*)d_in[8];
    float* out = (float*)d_out;

    float* pO;
    bf16 *pWh, *pWl, *pQKVh, *pQKVl;
    cudaGetSymbolAddress((void**)&pO, g_O);
    cudaGetSymbolAddress((void**)&pWh, g_Wh);
    cudaGetSymbolAddress((void**)&pWl, g_Wl);
    cudaGetSymbolAddress((void**)&pQKVh, g_QKVh);
    cudaGetSymbolAddress((void**)&pQKVl, g_QKVl);

    cudaFuncSetAttribute(gemm_wmma<0>, cudaFuncAttributeMaxDynamicSharedMemorySize, GEMM_SMEM);
    cudaFuncSetAttribute(gemm_wmma<1>, cudaFuncAttributeMaxDynamicSharedMemorySize, GEMM_SMEM);
    cudaFuncSetAttribute(attn_wmma, cudaFuncAttributeMaxDynamicSharedMemorySize, ATT_SMEM);

    const size_t QS = (size_t)MROWS * DM;

    build_w_all<<<dim3(DM, 4), 256>>>(wq_c, wk_c, wv_c, wo_c, pWh, pWl);

    gemm_wmma<1><<<dim3(8, 64, 3), 256, GEMM_SMEM>>>(
        x, pWh, pWl, wq_b, wk_b, wv_b, nullptr, pQKVh, pQKVl);

    attn_wmma<<<dim3(16, 64), 256, ATT_SMEM>>>(
        pQKVh, pQKVl, pQKVh + QS, pQKVl + QS, pQKVh + 2 * QS, pQKVl + 2 * QS, pO);

    gemm_wmma<0><<<dim3(8, 64, 1), 256, GEMM_SMEM>>>(
        pO, pWh + (size_t)3 * DM * DM, pWl + (size_t)3 * DM * DM,
        wo_b, nullptr, nullptr, out, nullptr, nullptr);
}